// round 8
// baseline (speedup 1.0000x reference)
#include <cuda_runtime.h>
#include <cuda_bf16.h>
#include <math.h>
#include <float.h>
#include <stdint.h>

#define D 128
#define KC 1024
#define BM 128          // rows per CTA
#define BNC 64          // codes per chunk
#define NCH (KC / BNC)  // 16 chunks
#define NTH 256
#define MARGIN 1e-4f

// ---- smem layout (bytes) ----
#define OFF_A    0                     // 128 x 512B  ([hi|lo] bf16, XOR swizzle) = 65536
#define OFF_B    65536                 // 2 x (64 x 512B) double buffer = 65536
#define BBUF     32768
#define OFF_CN   131072                // 2 x 64 floats = 512
#define OFF_XN   131584                // 128 f
#define OFF_RIDX 132096                // 128 i
#define OFF_SWR  132608                // 8 f
#define SMEM_TOTAL 132672

__device__ float __align__(16) g_cnorm[KC];
__device__ int g_counts[KC];
__device__ unsigned long long g_sse;
__device__ uint4 g_cbb4[KC * 32];      // bf16 codebook [hi|lo], 512B per code

__device__ __forceinline__ uint32_t smem_u32(const void* p) {
    uint32_t a;
    asm("{ .reg .u64 t; cvta.to.shared.u64 t, %1; cvt.u32.u64 %0, t; }" : "=r"(a) : "l"(p));
    return a;
}
#define CP_ASYNC16(dst, src) \
    asm volatile("cp.async.cg.shared.global [%0], [%1], 16;" :: "r"(dst), "l"(src))
#define CP_COMMIT() asm volatile("cp.async.commit_group;" ::: "memory")
#define CP_WAIT0()  asm volatile("cp.async.wait_group 0;" ::: "memory")

__device__ __forceinline__ void ldsm_x4(uint32_t& r0, uint32_t& r1, uint32_t& r2,
                                        uint32_t& r3, uint32_t addr) {
    asm volatile("ldmatrix.sync.aligned.m8n8.x4.shared.b16 {%0,%1,%2,%3}, [%4];"
                 : "=r"(r0), "=r"(r1), "=r"(r2), "=r"(r3) : "r"(addr));
}
__device__ __forceinline__ void mma16816(float* c, const uint32_t* a,
                                         uint32_t b0, uint32_t b1) {
    asm volatile("mma.sync.aligned.m16n8k16.row.col.f32.bf16.bf16.f32 "
                 "{%0,%1,%2,%3}, {%4,%5,%6,%7}, {%8,%9}, {%0,%1,%2,%3};"
                 : "+f"(c[0]), "+f"(c[1]), "+f"(c[2]), "+f"(c[3])
                 : "r"(a[0]), "r"(a[1]), "r"(a[2]), "r"(a[3]), "r"(b0), "r"(b1));
}
__device__ __forceinline__ void split2(float a, float b, uint32_t& hi, uint32_t& lo) {
    __nv_bfloat16 ha = __float2bfloat16(a), hb = __float2bfloat16(b);
    __nv_bfloat16 la = __float2bfloat16(a - __bfloat162float(ha));
    __nv_bfloat16 lb = __float2bfloat16(b - __bfloat162float(hb));
    hi = ((uint32_t)__bfloat16_as_ushort(hb) << 16) | __bfloat16_as_ushort(ha);
    lo = ((uint32_t)__bfloat16_as_ushort(lb) << 16) | __bfloat16_as_ushort(la);
}
__device__ __forceinline__ void upd2(float& m1, int& i1, float& m2, int& i2,
                                     float v, int k) {
    if (v < m1) { m2 = m1; i2 = i1; m1 = v; i1 = k; }
    else if (v < m2) { m2 = v; i2 = k; }
}
__device__ __forceinline__ void ins2(float& m1, int& i1, float& m2, int& i2,
                                     float v, int k) {
    bool lt1 = (v < m1) || (v == m1 && k < i1);
    if (lt1) { m2 = m1; i2 = i1; m1 = v; i1 = k; }
    else if ((v < m2) || (v == m2 && k < i2)) { m2 = v; i2 = k; }
}
// exact fp32 distance, identical op chain to R1 (x from global)
__device__ __forceinline__ float exact_dist(const float* xr, const float* cb,
                                            int k, float xn) {
    const float4* cr = (const float4*)(cb + (size_t)k * D);
    float acc = 0.f;
    #pragma unroll 8
    for (int d4 = 0; d4 < 32; ++d4) {
        float4 c4 = __ldg(cr + d4);
        const float* xp = xr + (d4 << 2);
        acc = fmaf(xp[0], c4.x, acc);
        acc = fmaf(xp[1], c4.y, acc);
        acc = fmaf(xp[2], c4.z, acc);
        acc = fmaf(xp[3], c4.w, acc);
    }
    return fmaxf(fmaf(-2.0f, acc, xn + g_cnorm[k]), 0.0f);
}

// ---------------- prep: c_norm + bf16 [hi|lo] codebook + zero counts/sse ----------------
__global__ void prep_kernel(const float* __restrict__ cb) {
    int tid = blockIdx.x * blockDim.x + threadIdx.x;
    if (tid < KC) g_counts[tid] = 0;
    if (tid == 0) g_sse = 0ull;
    int code = tid >> 5;
    int lane = tid & 31;
    const float4* cb4 = (const float4*)cb;
    float4 v = cb4[(size_t)code * 32 + lane];
    uint32_t* row = (uint32_t*)&g_cbb4[code * 32];
    uint32_t h01, l01, h23, l23;
    split2(v.x, v.y, h01, l01);
    split2(v.z, v.w, h23, l23);
    int p = lane * 2;
    row[p] = h01;      row[p + 1] = h23;      // hi block (256B)
    row[64 + p] = l01; row[64 + p + 1] = l23; // lo block (256B)
    float s = fmaf(v.x, v.x, fmaf(v.y, v.y, fmaf(v.z, v.z, v.w * v.w)));
    #pragma unroll
    for (int off = 16; off; off >>= 1)
        s += __shfl_down_sync(0xffffffffu, s, off);
    if (lane == 0) g_cnorm[code] = s;
}

// ---------------- main ----------------
__global__ __launch_bounds__(NTH, 1) void vq_main(
        const float* __restrict__ x, const float* __restrict__ cb,
        float* __restrict__ out, int nrows) {
    extern __shared__ char smem[];
    const uint32_t sbase = smem_u32(smem);
    float* sxn = (float*)(smem + OFF_XN);
    int*  ridx = (int*)(smem + OFF_RIDX);

    const int tid = threadIdx.x;
    const int wid = tid >> 5;
    const int lid = tid & 31;
    const int row0 = blockIdx.x * BM;

    // issue prefetch of B chunk 0 + scn chunk 0 (overlaps A build)
    {
        #pragma unroll
        for (int i = tid; i < BNC * 32; i += NTH) {
            int r = i >> 5, s = i & 31;
            uint32_t dst = sbase + OFF_B +
                (((uint32_t)(r * 512 + s * 16)) ^ ((uint32_t)(r & 7) << 4));
            CP_ASYNC16(dst, (const void*)&g_cbb4[r * 32 + s]);
        }
        if (tid < 16)
            CP_ASYNC16(sbase + OFF_CN + tid * 16, (const void*)(g_cnorm + tid * 4));
        CP_COMMIT();
    }

    // ---- stage A: bf16 [hi|lo] swizzled (512B/row) ----
    {
        const float4* xg4 = (const float4*)(x + (size_t)row0 * D);
        #pragma unroll
        for (int i = tid; i < BM * D / 4; i += NTH) {
            int r = i >> 5;
            int d = (i & 31) << 2;
            float4 v = xg4[i];
            uint32_t h01, l01, h23, l23;
            split2(v.x, v.y, h01, l01);
            split2(v.z, v.w, h23, l23);
            uint32_t rb = (uint32_t)r * 512;
            uint32_t sw = (uint32_t)(r & 7) << 4;
            uint32_t k0 = (uint32_t)d * 2;
            *(uint32_t*)(smem + OFF_A + ((rb + k0) ^ sw))           = h01;
            *(uint32_t*)(smem + OFF_A + ((rb + k0 + 4) ^ sw))       = h23;
            *(uint32_t*)(smem + OFF_A + ((rb + 256 + k0) ^ sw))     = l01;
            *(uint32_t*)(smem + OFF_A + ((rb + 256 + k0 + 4) ^ sw)) = l23;
        }
    }

    // exact per-row x norms from global (serial fmaf, bit-identical to R1)
    if (tid < BM) {
        const float* r = x + (size_t)(row0 + tid) * D;
        float s = 0.f;
        #pragma unroll 8
        for (int d = 0; d < D; ++d) s = fmaf(r[d], r[d], s);
        sxn[tid] = s;
    }
    CP_WAIT0();
    __syncthreads();

    const int wr = wid * 16;
    const float xn0 = sxn[wr + (lid >> 2)];
    const float xn1 = sxn[wr + (lid >> 2) + 8];

    const int rowA = wr + (lid & 15);
    const uint32_t swA = (uint32_t)(rowA & 7) << 4;
    const uint32_t aL0 = (uint32_t)(OFF_A + rowA * 512 + ((lid >> 4) << 4));
    const int rBn = lid & 15;
    const uint32_t swB = (uint32_t)(rBn & 7) << 4;
    const uint32_t bRow = (uint32_t)(rBn * 512 + ((lid >> 4) << 4));

    float m1a = FLT_MAX, m2a = FLT_MAX, m1b = FLT_MAX, m2b = FLT_MAX;
    int i1a = 0, i2a = 0, i1b = 0, i2b = 0;

    for (int ch = 0; ch < NCH; ++ch) {
        const int kc = ch * BNC;
        const int cur = ch & 1;
        // prefetch next chunk into the other buffer
        if (ch + 1 < NCH) {
            const int kn = kc + BNC;
            const int nxt = cur ^ 1;
            #pragma unroll
            for (int i = tid; i < BNC * 32; i += NTH) {
                int r = i >> 5, s = i & 31;
                uint32_t dst = sbase + OFF_B + nxt * BBUF +
                    (((uint32_t)(r * 512 + s * 16)) ^ ((uint32_t)(r & 7) << 4));
                CP_ASYNC16(dst, (const void*)&g_cbb4[(kn + r) * 32 + s]);
            }
            if (tid < 16)
                CP_ASYNC16(sbase + OFF_CN + nxt * 256 + tid * 16,
                           (const void*)(g_cnorm + kn + tid * 4));
            CP_COMMIT();
        }

        const uint32_t bL0 = (uint32_t)(OFF_B + cur * BBUF) + bRow;
        float acc[8][4];
        #pragma unroll
        for (int t = 0; t < 8; ++t)
            #pragma unroll
            for (int q = 0; q < 4; ++q) acc[t][q] = 0.f;

        // K split products: hi.hi + lo.hi + hi.lo, fragments reused per k-step
        #pragma unroll
        for (int ks = 0; ks < 8; ++ks) {
            uint32_t ahi[4], alo[4];
            ldsm_x4(ahi[0], ahi[1], ahi[2], ahi[3],
                    sbase + ((aL0 + ks * 32) ^ swA));
            ldsm_x4(alo[0], alo[1], alo[2], alo[3],
                    sbase + ((aL0 + 256 + ks * 32) ^ swA));
            #pragma unroll
            for (int p = 0; p < 4; ++p) {
                uint32_t bh0, bh1, bh2, bh3, bl0, bl1, bl2, bl3;
                ldsm_x4(bh0, bh1, bh2, bh3,
                        sbase + ((bL0 + p * 8192 + ks * 32) ^ swB));
                ldsm_x4(bl0, bl1, bl2, bl3,
                        sbase + ((bL0 + p * 8192 + 256 + ks * 32) ^ swB));
                mma16816(acc[2 * p],     ahi, bh0, bh2);
                mma16816(acc[2 * p + 1], ahi, bh1, bh3);
                mma16816(acc[2 * p],     alo, bh0, bh2);
                mma16816(acc[2 * p + 1], alo, bh1, bh3);
                mma16816(acc[2 * p],     ahi, bl0, bl2);
                mma16816(acc[2 * p + 1], ahi, bl1, bl3);
            }
        }

        // filter: approx dist, running top-2 per row slot (k ascending)
        const float* scn = (const float*)(smem + OFF_CN + cur * 256);
        #pragma unroll
        for (int nt = 0; nt < 8; ++nt) {
            int colb = nt * 8 + (lid & 3) * 2;
            float cn0 = scn[colb], cn1 = scn[colb + 1];
            float dv;
            dv = fmaxf(fmaf(-2.f, acc[nt][0], xn0 + cn0), 0.f);
            upd2(m1a, i1a, m2a, i2a, dv, kc + colb);
            dv = fmaxf(fmaf(-2.f, acc[nt][1], xn0 + cn1), 0.f);
            upd2(m1a, i1a, m2a, i2a, dv, kc + colb + 1);
            dv = fmaxf(fmaf(-2.f, acc[nt][2], xn1 + cn0), 0.f);
            upd2(m1b, i1b, m2b, i2b, dv, kc + colb);
            dv = fmaxf(fmaf(-2.f, acc[nt][3], xn1 + cn1), 0.f);
            upd2(m1b, i1b, m2b, i2b, dv, kc + colb + 1);
        }

        if (ch + 1 < NCH) CP_WAIT0();
        __syncthreads();
    }

    // merge top-2 across the 4 lanes of each quad (butterfly)
    #pragma unroll
    for (int off = 1; off <= 2; off <<= 1) {
        float om1 = __shfl_xor_sync(0xffffffffu, m1a, off);
        int   oi1 = __shfl_xor_sync(0xffffffffu, i1a, off);
        float om2 = __shfl_xor_sync(0xffffffffu, m2a, off);
        int   oi2 = __shfl_xor_sync(0xffffffffu, i2a, off);
        ins2(m1a, i1a, m2a, i2a, om1, oi1);
        ins2(m1a, i1a, m2a, i2a, om2, oi2);
        om1 = __shfl_xor_sync(0xffffffffu, m1b, off);
        oi1 = __shfl_xor_sync(0xffffffffu, i1b, off);
        om2 = __shfl_xor_sync(0xffffffffu, m2b, off);
        oi2 = __shfl_xor_sync(0xffffffffu, i2b, off);
        ins2(m1b, i1b, m2b, i2b, om1, oi1);
        ins2(m1b, i1b, m2b, i2b, om2, oi2);
    }

    // refine: exact fp32 recompute (R1 formula) over top-2, pick winner
    if ((lid & 3) == 0) {
        int r0l = wr + (lid >> 2);
        const float* xr0 = x + (size_t)(row0 + r0l) * D;
        int bi = i1a;
        float bd = exact_dist(xr0, cb, i1a, xn0);
        if (m2a < m1a + MARGIN) {
            float d2 = exact_dist(xr0, cb, i2a, xn0);
            if (d2 < bd || (d2 == bd && i2a < bi)) { bd = d2; bi = i2a; }
        }
        ridx[r0l] = bi;
        atomicAdd(&g_counts[bi], 1);

        int r1l = r0l + 8;
        const float* xr1 = x + (size_t)(row0 + r1l) * D;
        bi = i1b;
        bd = exact_dist(xr1, cb, i1b, xn1);
        if (m2b < m1b + MARGIN) {
            float d2 = exact_dist(xr1, cb, i2b, xn1);
            if (d2 < bd || (d2 == bd && i2b < bi)) { bd = d2; bi = i2b; }
        }
        ridx[r1l] = bi;
        atomicAdd(&g_counts[bi], 1);
    }
    __syncthreads();

    // output z_st = x + (z - x), accumulate sum((z-x)^2)  (identical math to R1)
    float lsse = 0.f;
    float4* og4 = (float4*)(out + (size_t)row0 * D);
    const float4* xg4 = (const float4*)(x + (size_t)row0 * D);
    #pragma unroll
    for (int i = tid; i < BM * D / 4; i += NTH) {
        int r = i >> 5;
        int idx = ridx[r];
        float4 zz = *(const float4*)(cb + (size_t)idx * D + ((i & 31) << 2));
        float4 xx = xg4[i];
        float4 o;
        float t0 = zz.x - xx.x; o.x = xx.x + t0;
        float t1 = zz.y - xx.y; o.y = xx.y + t1;
        float t2 = zz.z - xx.z; o.z = xx.z + t2;
        float t3 = zz.w - xx.w; o.w = xx.w + t3;
        lsse = fmaf(t0, t0, lsse);
        lsse = fmaf(t1, t1, lsse);
        lsse = fmaf(t2, t2, lsse);
        lsse = fmaf(t3, t3, lsse);
        og4[i] = o;
    }

    // deterministic fixed-point SSE accumulation
    #pragma unroll
    for (int off = 16; off; off >>= 1)
        lsse += __shfl_down_sync(0xffffffffu, lsse, off);
    float* swr = (float*)(smem + OFF_SWR);
    if (lid == 0) swr[wid] = lsse;
    __syncthreads();
    if (tid == 0) {
        float s = 0.f;
        #pragma unroll
        for (int w = 0; w < NTH / 32; ++w) s += swr[w];
        unsigned long long fx = (unsigned long long)((double)s * 1048576.0 + 0.5);
        atomicAdd(&g_sse, fx);
    }
}

__global__ void finalize_kernel(float* __restrict__ out, int ntot, int nrows) {
    __shared__ float red[32];
    int t = threadIdx.x;
    float p = (float)g_counts[t] / (float)nrows;
    float term = p * logf(p + 1e-10f);
    #pragma unroll
    for (int off = 16; off; off >>= 1)
        term += __shfl_down_sync(0xffffffffu, term, off);
    if ((t & 31) == 0) red[t >> 5] = term;
    __syncthreads();
    if (t < 32) {
        float v = red[t];
        #pragma unroll
        for (int off = 16; off; off >>= 1)
            v += __shfl_down_sync(0xffffffffu, v, off);
        if (t == 0) {
            float sse = (float)((double)g_sse * (1.0 / 1048576.0));
            float loss = sse / (float)ntot;
            out[ntot]     = loss;        // quantization_loss
            out[ntot + 1] = loss;        // commitment_loss (same forward value)
            out[ntot + 2] = expf(-v);    // perplexity
        }
    }
}

extern "C" void kernel_launch(void* const* d_in, const int* in_sizes, int n_in,
                              void* d_out, int out_size) {
    const float* x  = (const float*)d_in[0];
    const float* cb = (const float*)d_in[1];
    float* out = (float*)d_out;
    int ntot  = in_sizes[0];
    int nrows = ntot / D;

    cudaFuncSetAttribute(vq_main, cudaFuncAttributeMaxDynamicSharedMemorySize,
                         SMEM_TOTAL);

    prep_kernel<<<KC * 32 / NTH, NTH>>>(cb);
    vq_main<<<nrows / BM, NTH, SMEM_TOTAL>>>(x, cb, out, nrows);
    finalize_kernel<<<1, KC>>>(out, ntot, nrows);
}

// round 9
// speedup vs baseline: 1.4898x; 1.4898x over previous
#include <cuda_runtime.h>
#include <cuda_fp16.h>
#include <math.h>
#include <float.h>
#include <stdint.h>

#define D 128
#define KC 1024
#define BM 128          // rows per CTA
#define BNC 64          // codes per chunk
#define NCH (KC / BNC)  // 16 chunks
#define NTH 256
#define MARGIN 1e-4f

// ---- smem layout (bytes) ----
#define OFF_A    0                     // 128 x 256B fp16 (XOR swizzle) = 32768
#define OFF_B    32768                 // 2 x (64 x 256B) double buffer = 32768
#define BBUF     16384
#define OFF_CN   65536                 // 2 x 64 floats = 512
#define OFF_XN   66048                 // 128 f
#define OFF_RIDX 66560                 // 128 i
#define OFF_SWR  67072                 // 8 f
#define SMEM_TOTAL 67136

__device__ float __align__(16) g_cnorm[KC];
__device__ int g_counts[KC];
__device__ unsigned long long g_sse;
__device__ uint4 g_cbh[KC * 16];       // fp16 codebook, 256B per code

__device__ __forceinline__ uint32_t smem_u32(const void* p) {
    uint32_t a;
    asm("{ .reg .u64 t; cvta.to.shared.u64 t, %1; cvt.u32.u64 %0, t; }" : "=r"(a) : "l"(p));
    return a;
}
#define CP_ASYNC16(dst, src) \
    asm volatile("cp.async.cg.shared.global [%0], [%1], 16;" :: "r"(dst), "l"(src))
#define CP_COMMIT() asm volatile("cp.async.commit_group;" ::: "memory")
#define CP_WAIT0()  asm volatile("cp.async.wait_group 0;" ::: "memory")

__device__ __forceinline__ void ldsm_x4(uint32_t& r0, uint32_t& r1, uint32_t& r2,
                                        uint32_t& r3, uint32_t addr) {
    asm volatile("ldmatrix.sync.aligned.m8n8.x4.shared.b16 {%0,%1,%2,%3}, [%4];"
                 : "=r"(r0), "=r"(r1), "=r"(r2), "=r"(r3) : "r"(addr));
}
__device__ __forceinline__ void mma16816(float* c, const uint32_t* a,
                                         uint32_t b0, uint32_t b1) {
    asm volatile("mma.sync.aligned.m16n8k16.row.col.f32.f16.f16.f32 "
                 "{%0,%1,%2,%3}, {%4,%5,%6,%7}, {%8,%9}, {%0,%1,%2,%3};"
                 : "+f"(c[0]), "+f"(c[1]), "+f"(c[2]), "+f"(c[3])
                 : "r"(a[0]), "r"(a[1]), "r"(a[2]), "r"(a[3]), "r"(b0), "r"(b1));
}
__device__ __forceinline__ uint32_t packh2(float a, float b) {
    __half2 h = __floats2half2_rn(a, b);
    return *(uint32_t*)&h;
}
// top-3 update, strict < keeps earliest index (k iterated ascending)
__device__ __forceinline__ void upd3(float& m1, int& i1, float& m2, int& i2,
                                     float& m3, int& i3, float v, int k) {
    if (v < m1)      { m3 = m2; i3 = i2; m2 = m1; i2 = i1; m1 = v; i1 = k; }
    else if (v < m2) { m3 = m2; i3 = i2; m2 = v; i2 = k; }
    else if (v < m3) { m3 = v; i3 = k; }
}
// lexicographic (value, index) insert for cross-lane merge
__device__ __forceinline__ void ins3(float& m1, int& i1, float& m2, int& i2,
                                     float& m3, int& i3, float v, int k) {
    if (v < m1 || (v == m1 && k < i1)) {
        m3 = m2; i3 = i2; m2 = m1; i2 = i1; m1 = v; i1 = k;
    } else if (v < m2 || (v == m2 && k < i2)) {
        m3 = m2; i3 = i2; m2 = v; i2 = k;
    } else if (v < m3 || (v == m3 && k < i3)) {
        m3 = v; i3 = k;
    }
}
// exact fp32 distance, identical op chain to R1 (x from global)
__device__ __forceinline__ float exact_dist(const float* xr, const float* cb,
                                            int k, float xn) {
    const float4* cr = (const float4*)(cb + (size_t)k * D);
    float acc = 0.f;
    #pragma unroll 8
    for (int d4 = 0; d4 < 32; ++d4) {
        float4 c4 = __ldg(cr + d4);
        const float* xp = xr + (d4 << 2);
        acc = fmaf(xp[0], c4.x, acc);
        acc = fmaf(xp[1], c4.y, acc);
        acc = fmaf(xp[2], c4.z, acc);
        acc = fmaf(xp[3], c4.w, acc);
    }
    return fmaxf(fmaf(-2.0f, acc, xn + g_cnorm[k]), 0.0f);
}

// ---------------- prep: c_norm + fp16 codebook + zero counts/sse ----------------
__global__ void prep_kernel(const float* __restrict__ cb) {
    int tid = blockIdx.x * blockDim.x + threadIdx.x;
    if (tid < KC) g_counts[tid] = 0;
    if (tid == 0) g_sse = 0ull;
    int code = tid >> 5;
    int lane = tid & 31;
    const float4* cb4 = (const float4*)cb;
    float4 v = cb4[(size_t)code * 32 + lane];
    uint32_t* row = (uint32_t*)&g_cbh[code * 16];
    row[lane * 2]     = packh2(v.x, v.y);
    row[lane * 2 + 1] = packh2(v.z, v.w);
    float s = fmaf(v.x, v.x, fmaf(v.y, v.y, fmaf(v.z, v.z, v.w * v.w)));
    #pragma unroll
    for (int off = 16; off; off >>= 1)
        s += __shfl_down_sync(0xffffffffu, s, off);
    if (lane == 0) g_cnorm[code] = s;
}

// ---------------- main ----------------
__global__ __launch_bounds__(NTH, 2) void vq_main(
        const float* __restrict__ x, const float* __restrict__ cb,
        float* __restrict__ out, int nrows) {
    extern __shared__ char smem[];
    const uint32_t sbase = smem_u32(smem);
    float* sxn = (float*)(smem + OFF_XN);
    int*  ridx = (int*)(smem + OFF_RIDX);

    const int tid = threadIdx.x;
    const int wid = tid >> 5;
    const int lid = tid & 31;
    const int row0 = blockIdx.x * BM;

    // prefetch B chunk 0 + cnorm chunk 0 (overlaps A build)
    {
        #pragma unroll
        for (int i = tid; i < BNC * 16; i += NTH) {
            int r = i >> 4, s = i & 15;
            uint32_t dst = sbase + OFF_B +
                (((uint32_t)(r * 256 + s * 16)) ^ ((uint32_t)(r & 7) << 4));
            CP_ASYNC16(dst, (const void*)&g_cbh[r * 16 + s]);
        }
        if (tid < 16)
            CP_ASYNC16(sbase + OFF_CN + tid * 16, (const void*)(g_cnorm + tid * 4));
        CP_COMMIT();
    }

    // ---- stage A: fp16 x tile, swizzled (256B/row) ----
    {
        const float4* xg4 = (const float4*)(x + (size_t)row0 * D);
        #pragma unroll
        for (int i = tid; i < BM * D / 4; i += NTH) {
            int r = i >> 5;
            int d = (i & 31) << 2;
            float4 v = xg4[i];
            uint32_t rb = (uint32_t)r * 256;
            uint32_t sw = (uint32_t)(r & 7) << 4;
            uint32_t k0 = (uint32_t)d * 2;
            *(uint32_t*)(smem + OFF_A + ((rb + k0) ^ sw))     = packh2(v.x, v.y);
            *(uint32_t*)(smem + OFF_A + ((rb + k0 + 4) ^ sw)) = packh2(v.z, v.w);
        }
    }

    // exact per-row x norms from global (serial fmaf, bit-identical to R1)
    if (tid < BM) {
        const float* r = x + (size_t)(row0 + tid) * D;
        float s = 0.f;
        #pragma unroll 8
        for (int d = 0; d < D; ++d) s = fmaf(r[d], r[d], s);
        sxn[tid] = s;
    }
    CP_WAIT0();
    __syncthreads();

    const int wr = wid * 16;
    const float xn0 = sxn[wr + (lid >> 2)];
    const float xn1 = sxn[wr + (lid >> 2) + 8];

    const int rowA = wr + (lid & 15);
    const uint32_t swA = (uint32_t)(rowA & 7) << 4;
    const uint32_t aL0 = (uint32_t)(OFF_A + rowA * 256 + ((lid >> 4) << 4));
    const int rBn = lid & 15;
    const uint32_t swB = (uint32_t)(rBn & 7) << 4;
    const uint32_t bRow = (uint32_t)(rBn * 256 + ((lid >> 4) << 4));

    // top-3 filter state per row slot
    float m1a = FLT_MAX, m2a = FLT_MAX, m3a = FLT_MAX;
    float m1b = FLT_MAX, m2b = FLT_MAX, m3b = FLT_MAX;
    int i1a = 0, i2a = 0, i3a = 0, i1b = 0, i2b = 0, i3b = 0;

    for (int ch = 0; ch < NCH; ++ch) {
        const int kc = ch * BNC;
        const int cur = ch & 1;
        // prefetch next chunk into the other buffer
        if (ch + 1 < NCH) {
            const int kn = kc + BNC;
            const int nxt = cur ^ 1;
            #pragma unroll
            for (int i = tid; i < BNC * 16; i += NTH) {
                int r = i >> 4, s = i & 15;
                uint32_t dst = sbase + OFF_B + nxt * BBUF +
                    (((uint32_t)(r * 256 + s * 16)) ^ ((uint32_t)(r & 7) << 4));
                CP_ASYNC16(dst, (const void*)&g_cbh[(kn + r) * 16 + s]);
            }
            if (tid < 16)
                CP_ASYNC16(sbase + OFF_CN + nxt * 256 + tid * 16,
                           (const void*)(g_cnorm + kn + tid * 4));
            CP_COMMIT();
        }

        const uint32_t bL0 = (uint32_t)(OFF_B + cur * BBUF) + bRow;
        float acc[8][4];
        #pragma unroll
        for (int t = 0; t < 8; ++t)
            #pragma unroll
            for (int q = 0; q < 4; ++q) acc[t][q] = 0.f;

        // single-product fp16 GEMM: each acc touched once per k-step
        #pragma unroll
        for (int ks = 0; ks < 8; ++ks) {
            uint32_t a[4];
            ldsm_x4(a[0], a[1], a[2], a[3], sbase + ((aL0 + ks * 32) ^ swA));
            uint32_t b[4][4];
            #pragma unroll
            for (int p = 0; p < 4; ++p)
                ldsm_x4(b[p][0], b[p][1], b[p][2], b[p][3],
                        sbase + ((bL0 + p * 4096 + ks * 32) ^ swB));
            #pragma unroll
            for (int p = 0; p < 4; ++p) {
                mma16816(acc[2 * p],     a, b[p][0], b[p][2]);
                mma16816(acc[2 * p + 1], a, b[p][1], b[p][3]);
            }
        }

        // filter: approx dist, running top-3 per row slot (k ascending)
        const float* scn = (const float*)(smem + OFF_CN + cur * 256);
        #pragma unroll
        for (int nt = 0; nt < 8; ++nt) {
            int colb = nt * 8 + (lid & 3) * 2;
            float cn0 = scn[colb], cn1 = scn[colb + 1];
            float dv;
            dv = fmaxf(fmaf(-2.f, acc[nt][0], xn0 + cn0), 0.f);
            upd3(m1a, i1a, m2a, i2a, m3a, i3a, dv, kc + colb);
            dv = fmaxf(fmaf(-2.f, acc[nt][1], xn0 + cn1), 0.f);
            upd3(m1a, i1a, m2a, i2a, m3a, i3a, dv, kc + colb + 1);
            dv = fmaxf(fmaf(-2.f, acc[nt][2], xn1 + cn0), 0.f);
            upd3(m1b, i1b, m2b, i2b, m3b, i3b, dv, kc + colb);
            dv = fmaxf(fmaf(-2.f, acc[nt][3], xn1 + cn1), 0.f);
            upd3(m1b, i1b, m2b, i2b, m3b, i3b, dv, kc + colb + 1);
        }

        if (ch + 1 < NCH) CP_WAIT0();
        __syncthreads();
    }

    // merge top-3 across the 4 lanes of each quad (butterfly)
    #pragma unroll
    for (int off = 1; off <= 2; off <<= 1) {
        float om1 = __shfl_xor_sync(0xffffffffu, m1a, off);
        int   oi1 = __shfl_xor_sync(0xffffffffu, i1a, off);
        float om2 = __shfl_xor_sync(0xffffffffu, m2a, off);
        int   oi2 = __shfl_xor_sync(0xffffffffu, i2a, off);
        float om3 = __shfl_xor_sync(0xffffffffu, m3a, off);
        int   oi3 = __shfl_xor_sync(0xffffffffu, i3a, off);
        ins3(m1a, i1a, m2a, i2a, m3a, i3a, om1, oi1);
        ins3(m1a, i1a, m2a, i2a, m3a, i3a, om2, oi2);
        ins3(m1a, i1a, m2a, i2a, m3a, i3a, om3, oi3);
        om1 = __shfl_xor_sync(0xffffffffu, m1b, off);
        oi1 = __shfl_xor_sync(0xffffffffu, i1b, off);
        om2 = __shfl_xor_sync(0xffffffffu, m2b, off);
        oi2 = __shfl_xor_sync(0xffffffffu, i2b, off);
        om3 = __shfl_xor_sync(0xffffffffu, m3b, off);
        oi3 = __shfl_xor_sync(0xffffffffu, i3b, off);
        ins3(m1b, i1b, m2b, i2b, m3b, i3b, om1, oi1);
        ins3(m1b, i1b, m2b, i2b, m3b, i3b, om2, oi2);
        ins3(m1b, i1b, m2b, i2b, m3b, i3b, om3, oi3);
    }

    // refine: exact fp32 recompute (R1 formula) over top-3, pick winner
    if ((lid & 3) == 0) {
        int r0l = wr + (lid >> 2);
        const float* xr0 = x + (size_t)(row0 + r0l) * D;
        int bi = i1a;
        float bd = exact_dist(xr0, cb, i1a, xn0);
        if (m2a < m1a + MARGIN) {
            float d2 = exact_dist(xr0, cb, i2a, xn0);
            if (d2 < bd || (d2 == bd && i2a < bi)) { bd = d2; bi = i2a; }
        }
        if (m3a < m1a + MARGIN) {
            float d3 = exact_dist(xr0, cb, i3a, xn0);
            if (d3 < bd || (d3 == bd && i3a < bi)) { bd = d3; bi = i3a; }
        }
        ridx[r0l] = bi;
        atomicAdd(&g_counts[bi], 1);

        int r1l = r0l + 8;
        const float* xr1 = x + (size_t)(row0 + r1l) * D;
        bi = i1b;
        bd = exact_dist(xr1, cb, i1b, xn1);
        if (m2b < m1b + MARGIN) {
            float d2 = exact_dist(xr1, cb, i2b, xn1);
            if (d2 < bd || (d2 == bd && i2b < bi)) { bd = d2; bi = i2b; }
        }
        if (m3b < m1b + MARGIN) {
            float d3 = exact_dist(xr1, cb, i3b, xn1);
            if (d3 < bd || (d3 == bd && i3b < bi)) { bd = d3; bi = i3b; }
        }
        ridx[r1l] = bi;
        atomicAdd(&g_counts[bi], 1);
    }
    __syncthreads();

    // output z_st = x + (z - x), accumulate sum((z-x)^2)  (identical math to R1)
    float lsse = 0.f;
    float4* og4 = (float4*)(out + (size_t)row0 * D);
    const float4* xg4 = (const float4*)(x + (size_t)row0 * D);
    #pragma unroll
    for (int i = tid; i < BM * D / 4; i += NTH) {
        int r = i >> 5;
        int idx = ridx[r];
        float4 zz = *(const float4*)(cb + (size_t)idx * D + ((i & 31) << 2));
        float4 xx = xg4[i];
        float4 o;
        float t0 = zz.x - xx.x; o.x = xx.x + t0;
        float t1 = zz.y - xx.y; o.y = xx.y + t1;
        float t2 = zz.z - xx.z; o.z = xx.z + t2;
        float t3 = zz.w - xx.w; o.w = xx.w + t3;
        lsse = fmaf(t0, t0, lsse);
        lsse = fmaf(t1, t1, lsse);
        lsse = fmaf(t2, t2, lsse);
        lsse = fmaf(t3, t3, lsse);
        og4[i] = o;
    }

    // deterministic fixed-point SSE accumulation
    #pragma unroll
    for (int off = 16; off; off >>= 1)
        lsse += __shfl_down_sync(0xffffffffu, lsse, off);
    float* swr = (float*)(smem + OFF_SWR);
    if (lid == 0) swr[wid] = lsse;
    __syncthreads();
    if (tid == 0) {
        float s = 0.f;
        #pragma unroll
        for (int w = 0; w < NTH / 32; ++w) s += swr[w];
        unsigned long long fx = (unsigned long long)((double)s * 1048576.0 + 0.5);
        atomicAdd(&g_sse, fx);
    }
}

__global__ void finalize_kernel(float* __restrict__ out, int ntot, int nrows) {
    __shared__ float red[32];
    int t = threadIdx.x;
    float p = (float)g_counts[t] / (float)nrows;
    float term = p * logf(p + 1e-10f);
    #pragma unroll
    for (int off = 16; off; off >>= 1)
        term += __shfl_down_sync(0xffffffffu, term, off);
    if ((t & 31) == 0) red[t >> 5] = term;
    __syncthreads();
    if (t < 32) {
        float v = red[t];
        #pragma unroll
        for (int off = 16; off; off >>= 1)
            v += __shfl_down_sync(0xffffffffu, v, off);
        if (t == 0) {
            float sse = (float)((double)g_sse * (1.0 / 1048576.0));
            float loss = sse / (float)ntot;
            out[ntot]     = loss;        // quantization_loss
            out[ntot + 1] = loss;        // commitment_loss (same forward value)
            out[ntot + 2] = expf(-v);    // perplexity
        }
    }
}

extern "C" void kernel_launch(void* const* d_in, const int* in_sizes, int n_in,
                              void* d_out, int out_size) {
    const float* x  = (const float*)d_in[0];
    const float* cb = (const float*)d_in[1];
    float* out = (float*)d_out;
    int ntot  = in_sizes[0];
    int nrows = ntot / D;

    cudaFuncSetAttribute(vq_main, cudaFuncAttributeMaxDynamicSharedMemorySize,
                         SMEM_TOTAL);

    prep_kernel<<<KC * 32 / NTH, NTH>>>(cb);
    vq_main<<<nrows / BM, NTH, SMEM_TOTAL>>>(x, cb, out, nrows);
    finalize_kernel<<<1, KC>>>(out, ntot, nrows);
}

// round 12
// speedup vs baseline: 1.5851x; 1.0640x over previous
#include <cuda_runtime.h>
#include <cuda_bf16.h>
#include <math.h>
#include <float.h>
#include <stdint.h>

#define D 128
#define KC 1024
#define BM 128          // rows per CTA
#define BNC 64          // codes per chunk
#define NCH (KC / BNC)  // 16 chunks
#define NTH 256
#define GATE 32768u     // key-units; ~1.95e-3 in dist units (Δdist = Δkey * 2^-24)

// ---- smem layout (bytes) ----
#define OFF_A    0                     // 128 x 256B bf16 (XOR swizzle) = 32768
#define OFF_B    32768                 // 2 x (64 x 256B) double buffer = 32768
#define BBUF     16384
#define OFF_CC   65536                 // 2 x 64 floats = 512
#define OFF_XN   66048                 // 128 f
#define OFF_RIDX 66560                 // 128 i
#define OFF_SWR  67072                 // 8 f
#define SMEM_TOTAL 67136

__device__ float __align__(16) g_cnorm[KC];
__device__ float __align__(16) g_cc[KC];      // 88 - cnorm/8 (filter constant)
__device__ int g_counts[KC];
__device__ unsigned long long g_sse;
__device__ uint4 g_cbb[KC * 16];              // bf16 codebook, 256B per code

__device__ __forceinline__ uint32_t smem_u32(const void* p) {
    uint32_t a;
    asm("{ .reg .u64 t; cvta.to.shared.u64 t, %1; cvt.u32.u64 %0, t; }" : "=r"(a) : "l"(p));
    return a;
}
#define CP_ASYNC16(dst, src) \
    asm volatile("cp.async.cg.shared.global [%0], [%1], 16;" :: "r"(dst), "l"(src))
#define CP_COMMIT() asm volatile("cp.async.commit_group;" ::: "memory")
#define CP_WAIT0()  asm volatile("cp.async.wait_group 0;" ::: "memory")

__device__ __forceinline__ void ldsm_x4(uint32_t& r0, uint32_t& r1, uint32_t& r2,
                                        uint32_t& r3, uint32_t addr) {
    asm volatile("ldmatrix.sync.aligned.m8n8.x4.shared.b16 {%0,%1,%2,%3}, [%4];"
                 : "=r"(r0), "=r"(r1), "=r"(r2), "=r"(r3) : "r"(addr));
}
__device__ __forceinline__ void mma16816(float* c, const uint32_t* a,
                                         uint32_t b0, uint32_t b1) {
    asm volatile("mma.sync.aligned.m16n8k16.row.col.f32.bf16.bf16.f32 "
                 "{%0,%1,%2,%3}, {%4,%5,%6,%7}, {%8,%9}, {%0,%1,%2,%3};"
                 : "+f"(c[0]), "+f"(c[1]), "+f"(c[2]), "+f"(c[3])
                 : "r"(a[0]), "r"(a[1]), "r"(a[2]), "r"(a[3]), "r"(b0), "r"(b1));
}
__device__ __forceinline__ uint32_t packb2(float a, float b) {
    return ((uint32_t)__bfloat16_as_ushort(__float2bfloat16(b)) << 16) |
           __bfloat16_as_ushort(__float2bfloat16(a));
}
// exact fp32 distance, identical op chain to R1 (x from global)
__device__ __forceinline__ float exact_dist(const float* xr, const float* cb,
                                            int k, float xn) {
    const float4* cr = (const float4*)(cb + (size_t)k * D);
    float acc = 0.f;
    #pragma unroll 8
    for (int d4 = 0; d4 < 32; ++d4) {
        float4 c4 = __ldg(cr + d4);
        const float* xp = xr + (d4 << 2);
        acc = fmaf(xp[0], c4.x, acc);
        acc = fmaf(xp[1], c4.y, acc);
        acc = fmaf(xp[2], c4.z, acc);
        acc = fmaf(xp[3], c4.w, acc);
    }
    return fmaxf(fmaf(-2.0f, acc, xn + g_cnorm[k]), 0.0f);
}
// branchless top-3 insert of sorted-desc triple (keys: larger = better)
__device__ __forceinline__ void ins3k(uint32_t& m1, uint32_t& m2, uint32_t& m3,
                                      uint32_t q) {
    uint32_t t1 = min(m1, q); m1 = max(m1, q);
    uint32_t t2 = min(m2, t1); m2 = max(m2, t1);
    m3 = max(m3, t2);
}
// merge two sorted-desc triples into sorted-desc top-3
__device__ __forceinline__ void merge3(uint32_t& m1, uint32_t& m2, uint32_t& m3,
                                       uint32_t o1, uint32_t o2, uint32_t o3) {
    uint32_t x1 = max(m1, o1), y1 = min(m1, o1);
    uint32_t x2 = max(m2, o2), y2 = min(m2, o2);
    m1 = x1;
    uint32_t nm2 = max(y1, x2);
    m3 = max(min(y1, x2), max(y2, max(m3, o3)));
    m2 = nm2;
}

// ---------------- prep: cnorm + cc + bf16 codebook + zero counts/sse ----------------
__global__ void prep_kernel(const float* __restrict__ cb) {
    int tid = blockIdx.x * blockDim.x + threadIdx.x;
    if (tid < KC) g_counts[tid] = 0;
    if (tid == 0) g_sse = 0ull;
    int code = tid >> 5;
    int lane = tid & 31;
    const float4* cb4 = (const float4*)cb;
    float4 v = cb4[(size_t)code * 32 + lane];
    uint32_t* row = (uint32_t*)&g_cbb[code * 16];
    row[lane * 2]     = packb2(v.x, v.y);
    row[lane * 2 + 1] = packb2(v.z, v.w);
    float s = fmaf(v.x, v.x, fmaf(v.y, v.y, fmaf(v.z, v.z, v.w * v.w)));
    #pragma unroll
    for (int off = 16; off; off >>= 1)
        s += __shfl_down_sync(0xffffffffu, s, off);
    if (lane == 0) {
        g_cnorm[code] = s;
        g_cc[code] = 88.0f - s * 0.125f;
    }
}

// ---------------- main ----------------
__global__ __launch_bounds__(NTH, 2) void vq_main(
        const float* __restrict__ x, const float* __restrict__ cb,
        float* __restrict__ out, int nrows) {
    extern __shared__ char smem[];
    const uint32_t sbase = smem_u32(smem);
    float* sxn = (float*)(smem + OFF_XN);
    int*  ridx = (int*)(smem + OFF_RIDX);

    const int tid = threadIdx.x;
    const int wid = tid >> 5;
    const int lid = tid & 31;
    const int row0 = blockIdx.x * BM;

    // prefetch B chunk 0 + cc chunk 0 (overlaps A build)
    {
        #pragma unroll
        for (int i = tid; i < BNC * 16; i += NTH) {
            int r = i >> 4, s = i & 15;
            uint32_t dst = sbase + OFF_B +
                (((uint32_t)(r * 256 + s * 16)) ^ ((uint32_t)(r & 7) << 4));
            CP_ASYNC16(dst, (const void*)&g_cbb[r * 16 + s]);
        }
        if (tid < 16)
            CP_ASYNC16(sbase + OFF_CC + tid * 16, (const void*)(g_cc + tid * 4));
        CP_COMMIT();
    }

    // ---- stage A: bf16 x tile, swizzled (256B/row) ----
    {
        const float4* xg4 = (const float4*)(x + (size_t)row0 * D);
        #pragma unroll
        for (int i = tid; i < BM * D / 4; i += NTH) {
            int r = i >> 5;
            int d = (i & 31) << 2;
            float4 v = xg4[i];
            uint32_t rb = (uint32_t)r * 256;
            uint32_t sw = (uint32_t)(r & 7) << 4;
            uint32_t k0 = (uint32_t)d * 2;
            *(uint32_t*)(smem + OFF_A + ((rb + k0) ^ sw))     = packb2(v.x, v.y);
            *(uint32_t*)(smem + OFF_A + ((rb + k0 + 4) ^ sw)) = packb2(v.z, v.w);
        }
    }

    // exact per-row x norms from global (serial fmaf, bit-identical to R1)
    if (tid < BM) {
        const float* r = x + (size_t)(row0 + tid) * D;
        float s = 0.f;
        #pragma unroll 8
        for (int d = 0; d < D; ++d) s = fmaf(r[d], r[d], s);
        sxn[tid] = s;
    }
    CP_WAIT0();
    __syncthreads();

    const int wr = wid * 16;
    const float xn0 = sxn[wr + (lid >> 2)];
    const float xn1 = sxn[wr + (lid >> 2) + 8];

    const int rowA = wr + (lid & 15);
    const uint32_t swA = (uint32_t)(rowA & 7) << 4;
    const uint32_t aL0 = (uint32_t)(OFF_A + rowA * 256 + ((lid >> 4) << 4));
    const int rBn = lid & 15;
    const uint32_t swB = (uint32_t)(rBn & 7) << 4;
    const uint32_t bRow = (uint32_t)(rBn * 256 + ((lid >> 4) << 4));

    // hoist A fragments into registers (reused across all 16 chunks)
    uint32_t afr[8][4];
    #pragma unroll
    for (int ks = 0; ks < 8; ++ks)
        ldsm_x4(afr[ks][0], afr[ks][1], afr[ks][2], afr[ks][3],
                sbase + ((aL0 + ks * 32) ^ swA));

    // top-3 quad-key filter state per row slot (larger key = smaller dist)
    uint32_t m1a = 0, m2a = 0, m3a = 0, m1b = 0, m2b = 0, m3b = 0;

    for (int ch = 0; ch < NCH; ++ch) {
        const int kc = ch * BNC;
        const int cur = ch & 1;
        if (ch + 1 < NCH) {
            const int kn = kc + BNC;
            const int nxt = cur ^ 1;
            #pragma unroll
            for (int i = tid; i < BNC * 16; i += NTH) {
                int r = i >> 4, s = i & 15;
                uint32_t dst = sbase + OFF_B + nxt * BBUF +
                    (((uint32_t)(r * 256 + s * 16)) ^ ((uint32_t)(r & 7) << 4));
                CP_ASYNC16(dst, (const void*)&g_cbb[(kn + r) * 16 + s]);
            }
            if (tid < 16)
                CP_ASYNC16(sbase + OFF_CC + nxt * 256 + tid * 16,
                           (const void*)(g_cc + kn + tid * 4));
            CP_COMMIT();
        }

        const uint32_t bL0 = (uint32_t)(OFF_B + cur * BBUF) + bRow;
        float acc[8][4];
        #pragma unroll
        for (int t = 0; t < 8; ++t)
            #pragma unroll
            for (int q = 0; q < 4; ++q) acc[t][q] = 0.f;

        #pragma unroll
        for (int ks = 0; ks < 8; ++ks) {
            uint32_t b[4][4];
            #pragma unroll
            for (int p = 0; p < 4; ++p)
                ldsm_x4(b[p][0], b[p][1], b[p][2], b[p][3],
                        sbase + ((bL0 + p * 4096 + ks * 32) ^ swB));
            #pragma unroll
            for (int p = 0; p < 4; ++p) {
                mma16816(acc[2 * p],     afr[ks], b[p][0], b[p][2]);
                mma16816(acc[2 * p + 1], afr[ks], b[p][1], b[p][3]);
            }
        }

        // branchless quad-key filter: s'' = 0.25*dot + (88 - cn/8), exp pinned;
        // key = fbits*1024 + (1023 - base); track top-3 quad maxima.
        const float* ccp = (const float*)(smem + OFF_CC + cur * 256);
        #pragma unroll
        for (int g = 0; g < 4; ++g) {
            int cb0 = g * 16 + (lid & 3) * 2;
            float2 cA = *(const float2*)(ccp + cb0);
            float2 cB = *(const float2*)(ccp + cb0 + 8);
            uint32_t inv = 1023u - (uint32_t)(kc + cb0);
            // slot a (rows wr + lid>>2)
            uint32_t k0 = __float_as_uint(fmaf(acc[2*g][0],   0.25f, cA.x)) * 1024u + inv;
            uint32_t k1 = __float_as_uint(fmaf(acc[2*g][1],   0.25f, cA.y)) * 1024u + inv;
            uint32_t k2 = __float_as_uint(fmaf(acc[2*g+1][0], 0.25f, cB.x)) * 1024u + inv;
            uint32_t k3 = __float_as_uint(fmaf(acc[2*g+1][1], 0.25f, cB.y)) * 1024u + inv;
            ins3k(m1a, m2a, m3a, max(max(k0, k1), max(k2, k3)));
            // slot b (rows wr + 8 + lid>>2)
            k0 = __float_as_uint(fmaf(acc[2*g][2],   0.25f, cA.x)) * 1024u + inv;
            k1 = __float_as_uint(fmaf(acc[2*g][3],   0.25f, cA.y)) * 1024u + inv;
            k2 = __float_as_uint(fmaf(acc[2*g+1][2], 0.25f, cB.x)) * 1024u + inv;
            k3 = __float_as_uint(fmaf(acc[2*g+1][3], 0.25f, cB.y)) * 1024u + inv;
            ins3k(m1b, m2b, m3b, max(max(k0, k1), max(k2, k3)));
        }

        if (ch + 1 < NCH) CP_WAIT0();
        __syncthreads();
    }

    // merge top-3 quad keys across the 4 lanes of each quad (butterfly)
    #pragma unroll
    for (int off = 1; off <= 2; off <<= 1) {
        uint32_t o1 = __shfl_xor_sync(0xffffffffu, m1a, off);
        uint32_t o2 = __shfl_xor_sync(0xffffffffu, m2a, off);
        uint32_t o3 = __shfl_xor_sync(0xffffffffu, m3a, off);
        merge3(m1a, m2a, m3a, o1, o2, o3);
        o1 = __shfl_xor_sync(0xffffffffu, m1b, off);
        o2 = __shfl_xor_sync(0xffffffffu, m2b, off);
        o3 = __shfl_xor_sync(0xffffffffu, m3b, off);
        merge3(m1b, m2b, m3b, o1, o2, o3);
    }

    // refine: expand gated quads, all 4 quad-lanes compute exact dists in parallel
    {
        const int moff = (lid & 1) + ((lid >> 1) & 1) * 8;  // {0,1,8,9}
        uint32_t mq[2][3] = {{m1a, m2a, m3a}, {m1b, m2b, m3b}};
        #pragma unroll
        for (int sl = 0; sl < 2; ++sl) {
            int row = wr + (lid >> 2) + sl * 8;
            const float* xr = x + (size_t)(row0 + row) * D;
            float xn = sl ? xn1 : xn0;
            unsigned long long best = 0xFFFFFFFFFFFFFFFFull;
            #pragma unroll
            for (int t = 0; t < 3; ++t) {
                if (mq[sl][0] - mq[sl][t] < GATE) {   // uniform across quad lanes
                    int k = (int)(1023u - (mq[sl][t] & 1023u)) + moff;
                    float dd = exact_dist(xr, cb, k, xn);
                    unsigned long long pk =
                        ((unsigned long long)__float_as_uint(dd) << 32) | (unsigned)k;
                    best = best < pk ? best : pk;
                }
            }
            // lexicographic min across the 4 quad lanes
            #pragma unroll
            for (int off = 1; off <= 2; off <<= 1) {
                unsigned long long o = __shfl_xor_sync(0xffffffffu, best, off);
                best = best < o ? best : o;
            }
            if ((lid & 3) == 0) {
                int bi = (int)(best & 0xFFFFFFFFull);
                ridx[row] = bi;
                atomicAdd(&g_counts[bi], 1);
            }
        }
    }
    __syncthreads();

    // output z_st = x + (z - x), accumulate sum((z-x)^2)  (identical math to R1)
    float lsse = 0.f;
    float4* og4 = (float4*)(out + (size_t)row0 * D);
    const float4* xg4 = (const float4*)(x + (size_t)row0 * D);
    #pragma unroll
    for (int i = tid; i < BM * D / 4; i += NTH) {
        int r = i >> 5;
        int idx = ridx[r];
        float4 zz = *(const float4*)(cb + (size_t)idx * D + ((i & 31) << 2));
        float4 xx = xg4[i];
        float4 o;
        float t0 = zz.x - xx.x; o.x = xx.x + t0;
        float t1 = zz.y - xx.y; o.y = xx.y + t1;
        float t2 = zz.z - xx.z; o.z = xx.z + t2;
        float t3 = zz.w - xx.w; o.w = xx.w + t3;
        lsse = fmaf(t0, t0, lsse);
        lsse = fmaf(t1, t1, lsse);
        lsse = fmaf(t2, t2, lsse);
        lsse = fmaf(t3, t3, lsse);
        og4[i] = o;
    }

    // deterministic fixed-point SSE accumulation
    #pragma unroll
    for (int off = 16; off; off >>= 1)
        lsse += __shfl_down_sync(0xffffffffu, lsse, off);
    float* swr = (float*)(smem + OFF_SWR);
    if (lid == 0) swr[wid] = lsse;
    __syncthreads();
    if (tid == 0) {
        float s = 0.f;
        #pragma unroll
        for (int w = 0; w < NTH / 32; ++w) s += swr[w];
        unsigned long long fx = (unsigned long long)((double)s * 1048576.0 + 0.5);
        atomicAdd(&g_sse, fx);
    }
}

__global__ void finalize_kernel(float* __restrict__ out, int ntot, int nrows) {
    __shared__ float red[32];
    int t = threadIdx.x;
    float p = (float)g_counts[t] / (float)nrows;
    float term = p * logf(p + 1e-10f);
    #pragma unroll
    for (int off = 16; off; off >>= 1)
        term += __shfl_down_sync(0xffffffffu, term, off);
    if ((t & 31) == 0) red[t >> 5] = term;
    __syncthreads();
    if (t < 32) {
        float v = red[t];
        #pragma unroll
        for (int off = 16; off; off >>= 1)
            v += __shfl_down_sync(0xffffffffu, v, off);
        if (t == 0) {
            float sse = (float)((double)g_sse * (1.0 / 1048576.0));
            float loss = sse / (float)ntot;
            out[ntot]     = loss;        // quantization_loss
            out[ntot + 1] = loss;        // commitment_loss (same forward value)
            out[ntot + 2] = expf(-v);    // perplexity
        }
    }
}

extern "C" void kernel_launch(void* const* d_in, const int* in_sizes, int n_in,
                              void* d_out, int out_size) {
    const float* x  = (const float*)d_in[0];
    const float* cb = (const float*)d_in[1];
    float* out = (float*)d_out;
    int ntot  = in_sizes[0];
    int nrows = ntot / D;

    cudaFuncSetAttribute(vq_main, cudaFuncAttributeMaxDynamicSharedMemorySize,
                         SMEM_TOTAL);

    prep_kernel<<<KC * 32 / NTH, NTH>>>(cb);
    vq_main<<<nrows / BM, NTH, SMEM_TOTAL>>>(x, cb, out, nrows);
    finalize_kernel<<<1, KC>>>(out, ntot, nrows);
}

// round 15
// speedup vs baseline: 1.6012x; 1.0102x over previous
#include <cuda_runtime.h>
#include <cuda_fp16.h>
#include <math.h>
#include <float.h>
#include <stdint.h>

#define D 128
#define KC 1024
#define BM 128          // rows per CTA
#define BNC 64          // codes per chunk
#define NCH (KC / BNC)  // 16 chunks
#define NTH 256
#define GATE 32768u     // key-units; ~1.95e-3 in dist units

// ---- smem layout (bytes) ----
#define OFF_A    0                     // 128 x 256B fp16 (XOR swizzle) = 32768
#define OFF_B    32768                 // 2 x (64 x 256B) double buffer = 32768
#define BBUF     16384
#define OFF_CC   65536                 // 2 x 64 floats = 512
#define OFF_XN   66048                 // 128 f
#define OFF_RIDX 66560                 // 128 i
#define OFF_SWR  67072                 // 8 f
#define SMEM_TOTAL 67136

__device__ float __align__(16) g_cnorm[KC];
__device__ float __align__(16) g_cc[KC];      // 88 - cnorm/8 (filter constant)
__device__ int g_counts[KC];
__device__ unsigned long long g_sse;
__device__ uint4 g_cbh[KC * 16];              // fp16 codebook, 256B per code

__device__ __forceinline__ uint32_t smem_u32(const void* p) {
    uint32_t a;
    asm("{ .reg .u64 t; cvta.to.shared.u64 t, %1; cvt.u32.u64 %0, t; }" : "=r"(a) : "l"(p));
    return a;
}
#define CP_ASYNC16(dst, src) \
    asm volatile("cp.async.cg.shared.global [%0], [%1], 16;" :: "r"(dst), "l"(src))
#define CP_COMMIT() asm volatile("cp.async.commit_group;" ::: "memory")
#define CP_WAIT0()  asm volatile("cp.async.wait_group 0;" ::: "memory")

__device__ __forceinline__ void ldsm_x4(uint32_t& r0, uint32_t& r1, uint32_t& r2,
                                        uint32_t& r3, uint32_t addr) {
    asm volatile("ldmatrix.sync.aligned.m8n8.x4.shared.b16 {%0,%1,%2,%3}, [%4];"
                 : "=r"(r0), "=r"(r1), "=r"(r2), "=r"(r3) : "r"(addr));
}
// fp16 accumulate HMMA: C(f16x2 x2) = A(f16) * B(f16) + C
__device__ __forceinline__ void mma16816h(uint32_t* c, const uint32_t* a,
                                          uint32_t b0, uint32_t b1) {
    asm volatile("mma.sync.aligned.m16n8k16.row.col.f16.f16.f16.f16 "
                 "{%0,%1}, {%2,%3,%4,%5}, {%6,%7}, {%0,%1};"
                 : "+r"(c[0]), "+r"(c[1])
                 : "r"(a[0]), "r"(a[1]), "r"(a[2]), "r"(a[3]), "r"(b0), "r"(b1));
}
__device__ __forceinline__ uint32_t packh2(float a, float b) {
    __half2 h = __floats2half2_rn(a, b);
    return *(uint32_t*)&h;
}
__device__ __forceinline__ float2 h22f2(uint32_t v) {
    return __half22float2(*(__half2*)&v);
}
// exact fp32 distance, identical op chain to R1 (x from global)
__device__ __forceinline__ float exact_dist(const float* xr, const float* cb,
                                            int k, float xn) {
    const float4* cr = (const float4*)(cb + (size_t)k * D);
    float acc = 0.f;
    #pragma unroll 8
    for (int d4 = 0; d4 < 32; ++d4) {
        float4 c4 = __ldg(cr + d4);
        const float* xp = xr + (d4 << 2);
        acc = fmaf(xp[0], c4.x, acc);
        acc = fmaf(xp[1], c4.y, acc);
        acc = fmaf(xp[2], c4.z, acc);
        acc = fmaf(xp[3], c4.w, acc);
    }
    return fmaxf(fmaf(-2.0f, acc, xn + g_cnorm[k]), 0.0f);
}
// branchless top-3 insert of sorted-desc triple (keys: larger = better)
__device__ __forceinline__ void ins3k(uint32_t& m1, uint32_t& m2, uint32_t& m3,
                                      uint32_t q) {
    uint32_t t1 = min(m1, q); m1 = max(m1, q);
    uint32_t t2 = min(m2, t1); m2 = max(m2, t1);
    m3 = max(m3, t2);
}
// merge two sorted-desc triples into sorted-desc top-3
__device__ __forceinline__ void merge3(uint32_t& m1, uint32_t& m2, uint32_t& m3,
                                       uint32_t o1, uint32_t o2, uint32_t o3) {
    uint32_t x1 = max(m1, o1), y1 = min(m1, o1);
    uint32_t x2 = max(m2, o2), y2 = min(m2, o2);
    m1 = x1;
    uint32_t nm2 = max(y1, x2);
    m3 = max(min(y1, x2), max(y2, max(m3, o3)));
    m2 = nm2;
}

// ---------------- prep: cnorm + cc + fp16 codebook + zero counts/sse ----------------
__global__ void prep_kernel(const float* __restrict__ cb) {
    int tid = blockIdx.x * blockDim.x + threadIdx.x;
    if (tid < KC) g_counts[tid] = 0;
    if (tid == 0) g_sse = 0ull;
    int code = tid >> 5;
    int lane = tid & 31;
    const float4* cb4 = (const float4*)cb;
    float4 v = cb4[(size_t)code * 32 + lane];
    uint32_t* row = (uint32_t*)&g_cbh[code * 16];
    row[lane * 2]     = packh2(v.x, v.y);
    row[lane * 2 + 1] = packh2(v.z, v.w);
    float s = fmaf(v.x, v.x, fmaf(v.y, v.y, fmaf(v.z, v.z, v.w * v.w)));
    #pragma unroll
    for (int off = 16; off; off >>= 1)
        s += __shfl_down_sync(0xffffffffu, s, off);
    if (lane == 0) {
        g_cnorm[code] = s;
        g_cc[code] = 88.0f - s * 0.125f;
    }
}

// ---------------- main ----------------
__global__ __launch_bounds__(NTH, 2) void vq_main(
        const float* __restrict__ x, const float* __restrict__ cb,
        float* __restrict__ out, int nrows) {
    extern __shared__ char smem[];
    const uint32_t sbase = smem_u32(smem);
    float* sxn = (float*)(smem + OFF_XN);
    int*  ridx = (int*)(smem + OFF_RIDX);

    const int tid = threadIdx.x;
    const int wid = tid >> 5;
    const int lid = tid & 31;
    const int row0 = blockIdx.x * BM;

    // prefetch B chunk 0 + cc chunk 0 (overlaps A build)
    {
        #pragma unroll
        for (int i = tid; i < BNC * 16; i += NTH) {
            int r = i >> 4, s = i & 15;
            uint32_t dst = sbase + OFF_B +
                (((uint32_t)(r * 256 + s * 16)) ^ ((uint32_t)(r & 7) << 4));
            CP_ASYNC16(dst, (const void*)&g_cbh[r * 16 + s]);
        }
        if (tid < 16)
            CP_ASYNC16(sbase + OFF_CC + tid * 16, (const void*)(g_cc + tid * 4));
        CP_COMMIT();
    }

    // ---- stage A: fp16 x tile, swizzled (256B/row) ----
    {
        const float4* xg4 = (const float4*)(x + (size_t)row0 * D);
        #pragma unroll
        for (int i = tid; i < BM * D / 4; i += NTH) {
            int r = i >> 5;
            int d = (i & 31) << 2;
            float4 v = xg4[i];
            uint32_t rb = (uint32_t)r * 256;
            uint32_t sw = (uint32_t)(r & 7) << 4;
            uint32_t k0 = (uint32_t)d * 2;
            *(uint32_t*)(smem + OFF_A + ((rb + k0) ^ sw))     = packh2(v.x, v.y);
            *(uint32_t*)(smem + OFF_A + ((rb + k0 + 4) ^ sw)) = packh2(v.z, v.w);
        }
    }

    // exact per-row x norms from global (serial fmaf, bit-identical to R1)
    if (tid < BM) {
        const float* r = x + (size_t)(row0 + tid) * D;
        float s = 0.f;
        #pragma unroll 8
        for (int d = 0; d < D; ++d) s = fmaf(r[d], r[d], s);
        sxn[tid] = s;
    }
    CP_WAIT0();
    __syncthreads();

    const int wr = wid * 16;
    const float xn0 = sxn[wr + (lid >> 2)];
    const float xn1 = sxn[wr + (lid >> 2) + 8];

    const int rowA = wr + (lid & 15);
    const uint32_t swA = (uint32_t)(rowA & 7) << 4;
    const uint32_t aL0 = (uint32_t)(OFF_A + rowA * 256 + ((lid >> 4) << 4));
    const int rBn = lid & 15;
    const uint32_t swB = (uint32_t)(rBn & 7) << 4;
    const uint32_t bRow = (uint32_t)(rBn * 256 + ((lid >> 4) << 4));

    // hoist A fragments into registers (reused across all 16 chunks)
    uint32_t afr[8][4];
    #pragma unroll
    for (int ks = 0; ks < 8; ++ks)
        ldsm_x4(afr[ks][0], afr[ks][1], afr[ks][2], afr[ks][3],
                sbase + ((aL0 + ks * 32) ^ swA));

    // top-3 quad-key filter state per row slot (larger key = smaller dist)
    uint32_t m1a = 0, m2a = 0, m3a = 0, m1b = 0, m2b = 0, m3b = 0;

    for (int ch = 0; ch < NCH; ++ch) {
        const int kc = ch * BNC;
        const int cur = ch & 1;
        if (ch + 1 < NCH) {
            const int kn = kc + BNC;
            const int nxt = cur ^ 1;
            #pragma unroll
            for (int i = tid; i < BNC * 16; i += NTH) {
                int r = i >> 4, s = i & 15;
                uint32_t dst = sbase + OFF_B + nxt * BBUF +
                    (((uint32_t)(r * 256 + s * 16)) ^ ((uint32_t)(r & 7) << 4));
                CP_ASYNC16(dst, (const void*)&g_cbh[(kn + r) * 16 + s]);
            }
            if (tid < 16)
                CP_ASYNC16(sbase + OFF_CC + nxt * 256 + tid * 16,
                           (const void*)(g_cc + kn + tid * 4));
            CP_COMMIT();
        }

        const uint32_t bL0 = (uint32_t)(OFF_B + cur * BBUF) + bRow;
        // fp16x2 accumulators: [n-tile][0]=rows wr+(lid>>2), [1]=rows +8
        uint32_t acc2[8][2];
        #pragma unroll
        for (int t = 0; t < 8; ++t) { acc2[t][0] = 0u; acc2[t][1] = 0u; }

        #pragma unroll
        for (int ks = 0; ks < 8; ++ks) {
            uint32_t b[4][4];
            #pragma unroll
            for (int p = 0; p < 4; ++p)
                ldsm_x4(b[p][0], b[p][1], b[p][2], b[p][3],
                        sbase + ((bL0 + p * 4096 + ks * 32) ^ swB));
            #pragma unroll
            for (int p = 0; p < 4; ++p) {
                mma16816h(acc2[2 * p],     afr[ks], b[p][0], b[p][2]);
                mma16816h(acc2[2 * p + 1], afr[ks], b[p][1], b[p][3]);
            }
        }

        // branchless quad-key filter: s'' = 0.25*dot + (88 - cn/8), exp pinned;
        // key = fbits*1024 + (1023 - base); track top-3 quad maxima.
        const float* ccp = (const float*)(smem + OFF_CC + cur * 256);
        #pragma unroll
        for (int g = 0; g < 4; ++g) {
            int cb0 = g * 16 + (lid & 3) * 2;
            float2 cA = *(const float2*)(ccp + cb0);
            float2 cB = *(const float2*)(ccp + cb0 + 8);
            uint32_t inv = 1023u - (uint32_t)(kc + cb0);
            // slot a (rows wr + lid>>2): cols cb0,cb0+1 and cb0+8,cb0+9
            float2 fa0 = h22f2(acc2[2 * g][0]);
            float2 fa1 = h22f2(acc2[2 * g + 1][0]);
            uint32_t k0 = __float_as_uint(fmaf(fa0.x, 0.25f, cA.x)) * 1024u + inv;
            uint32_t k1 = __float_as_uint(fmaf(fa0.y, 0.25f, cA.y)) * 1024u + inv;
            uint32_t k2 = __float_as_uint(fmaf(fa1.x, 0.25f, cB.x)) * 1024u + inv;
            uint32_t k3 = __float_as_uint(fmaf(fa1.y, 0.25f, cB.y)) * 1024u + inv;
            ins3k(m1a, m2a, m3a, max(max(k0, k1), max(k2, k3)));
            // slot b (rows wr + 8 + lid>>2)
            float2 fb0 = h22f2(acc2[2 * g][1]);
            float2 fb1 = h22f2(acc2[2 * g + 1][1]);
            k0 = __float_as_uint(fmaf(fb0.x, 0.25f, cA.x)) * 1024u + inv;
            k1 = __float_as_uint(fmaf(fb0.y, 0.25f, cA.y)) * 1024u + inv;
            k2 = __float_as_uint(fmaf(fb1.x, 0.25f, cB.x)) * 1024u + inv;
            k3 = __float_as_uint(fmaf(fb1.y, 0.25f, cB.y)) * 1024u + inv;
            ins3k(m1b, m2b, m3b, max(max(k0, k1), max(k2, k3)));
        }

        if (ch + 1 < NCH) CP_WAIT0();
        __syncthreads();
    }

    // merge top-3 quad keys across the 4 lanes of each quad (butterfly)
    #pragma unroll
    for (int off = 1; off <= 2; off <<= 1) {
        uint32_t o1 = __shfl_xor_sync(0xffffffffu, m1a, off);
        uint32_t o2 = __shfl_xor_sync(0xffffffffu, m2a, off);
        uint32_t o3 = __shfl_xor_sync(0xffffffffu, m3a, off);
        merge3(m1a, m2a, m3a, o1, o2, o3);
        o1 = __shfl_xor_sync(0xffffffffu, m1b, off);
        o2 = __shfl_xor_sync(0xffffffffu, m2b, off);
        o3 = __shfl_xor_sync(0xffffffffu, m3b, off);
        merge3(m1b, m2b, m3b, o1, o2, o3);
    }

    // refine: expand gated quads, all 4 quad-lanes compute exact dists in parallel
    {
        const int moff = (lid & 1) + ((lid >> 1) & 1) * 8;  // {0,1,8,9}
        uint32_t mq[2][3] = {{m1a, m2a, m3a}, {m1b, m2b, m3b}};
        #pragma unroll
        for (int sl = 0; sl < 2; ++sl) {
            int row = wr + (lid >> 2) + sl * 8;
            const float* xr = x + (size_t)(row0 + row) * D;
            float xn = sl ? xn1 : xn0;
            unsigned long long best = 0xFFFFFFFFFFFFFFFFull;
            #pragma unroll
            for (int t = 0; t < 3; ++t) {
                if (mq[sl][0] - mq[sl][t] < GATE) {   // uniform across quad lanes
                    int k = (int)(1023u - (mq[sl][t] & 1023u)) + moff;
                    float dd = exact_dist(xr, cb, k, xn);
                    unsigned long long pk =
                        ((unsigned long long)__float_as_uint(dd) << 32) | (unsigned)k;
                    best = best < pk ? best : pk;
                }
            }
            #pragma unroll
            for (int off = 1; off <= 2; off <<= 1) {
                unsigned long long o = __shfl_xor_sync(0xffffffffu, best, off);
                best = best < o ? best : o;
            }
            if ((lid & 3) == 0) {
                int bi = (int)(best & 0xFFFFFFFFull);
                ridx[row] = bi;
                atomicAdd(&g_counts[bi], 1);
            }
        }
    }
    __syncthreads();

    // output z_st = x + (z - x), accumulate sum((z-x)^2)  (identical math to R1)
    float lsse = 0.f;
    float4* og4 = (float4*)(out + (size_t)row0 * D);
    const float4* xg4 = (const float4*)(x + (size_t)row0 * D);
    #pragma unroll
    for (int i = tid; i < BM * D / 4; i += NTH) {
        int r = i >> 5;
        int idx = ridx[r];
        float4 zz = *(const float4*)(cb + (size_t)idx * D + ((i & 31) << 2));
        float4 xx = xg4[i];
        float4 o;
        float t0 = zz.x - xx.x; o.x = xx.x + t0;
        float t1 = zz.y - xx.y; o.y = xx.y + t1;
        float t2 = zz.z - xx.z; o.z = xx.z + t2;
        float t3 = zz.w - xx.w; o.w = xx.w + t3;
        lsse = fmaf(t0, t0, lsse);
        lsse = fmaf(t1, t1, lsse);
        lsse = fmaf(t2, t2, lsse);
        lsse = fmaf(t3, t3, lsse);
        og4[i] = o;
    }

    // deterministic fixed-point SSE accumulation
    #pragma unroll
    for (int off = 16; off; off >>= 1)
        lsse += __shfl_down_sync(0xffffffffu, lsse, off);
    float* swr = (float*)(smem + OFF_SWR);
    if (lid == 0) swr[wid] = lsse;
    __syncthreads();
    if (tid == 0) {
        float s = 0.f;
        #pragma unroll
        for (int w = 0; w < NTH / 32; ++w) s += swr[w];
        unsigned long long fx = (unsigned long long)((double)s * 1048576.0 + 0.5);
        atomicAdd(&g_sse, fx);
    }
}

__global__ void finalize_kernel(float* __restrict__ out, int ntot, int nrows) {
    __shared__ float red[32];
    int t = threadIdx.x;
    float p = (float)g_counts[t] / (float)nrows;
    float term = p * logf(p + 1e-10f);
    #pragma unroll
    for (int off = 16; off; off >>= 1)
        term += __shfl_down_sync(0xffffffffu, term, off);
    if ((t & 31) == 0) red[t >> 5] = term;
    __syncthreads();
    if (t < 32) {
        float v = red[t];
        #pragma unroll
        for (int off = 16; off; off >>= 1)
            v += __shfl_down_sync(0xffffffffu, v, off);
        if (t == 0) {
            float sse = (float)((double)g_sse * (1.0 / 1048576.0));
            float loss = sse / (float)ntot;
            out[ntot]     = loss;        // quantization_loss
            out[ntot + 1] = loss;        // commitment_loss (same forward value)
            out[ntot + 2] = expf(-v);    // perplexity
        }
    }
}

extern "C" void kernel_launch(void* const* d_in, const int* in_sizes, int n_in,
                              void* d_out, int out_size) {
    const float* x  = (const float*)d_in[0];
    const float* cb = (const float*)d_in[1];
    float* out = (float*)d_out;
    int ntot  = in_sizes[0];
    int nrows = ntot / D;

    cudaFuncSetAttribute(vq_main, cudaFuncAttributeMaxDynamicSharedMemorySize,
                         SMEM_TOTAL);

    prep_kernel<<<KC * 32 / NTH, NTH>>>(cb);
    vq_main<<<nrows / BM, NTH, SMEM_TOTAL>>>(x, cb, out, nrows);
    finalize_kernel<<<1, KC>>>(out, ntot, nrows);
}